// round 1
// baseline (speedup 1.0000x reference)
#include <cuda_runtime.h>
#include <math.h>

#define BB 2
#define SS 2048
#define DD 1024
#define HH 16
#define HD 64
#define MTOT (BB*SS)   // 4096 rows

// Scratch (allocation-free rule: device globals)
__device__ float g_q[MTOT*DD];
__device__ float g_k[MTOT*DD];
__device__ float g_v[MTOT*DD];
__device__ float g_att[MTOT*DD];

// ---------------------------------------------------------------------------
// GEMM: C[M,N] = A[M,K] * B[N,K]^T   (both A and B are K-contiguous row-major)
// 128x128 block tile, 8x8 per-thread tile, BK=8, 256 threads.
// ---------------------------------------------------------------------------
__global__ __launch_bounds__(256, 2)
void gemm_nt_kernel(const float* __restrict__ A, const float* __restrict__ B,
                    float* __restrict__ C, int M, int N, int K) {
    __shared__ float As[8][132];
    __shared__ float Bs[8][132];

    const int tid = threadIdx.x;
    const int tx  = tid & 15;        // 0..15 -> N dim
    const int ty  = tid >> 4;        // 0..15 -> M dim
    const int m0  = blockIdx.y * 128;
    const int n0  = blockIdx.x * 128;

    const int arow = tid >> 1;             // 0..127
    const int ac   = (tid & 1) * 4;        // 0 or 4

    const float* Aptr = A + (size_t)(m0 + arow) * K + ac;
    const float* Bptr = B + (size_t)(n0 + arow) * K + ac;

    float acc[8][8];
    #pragma unroll
    for (int i = 0; i < 8; i++)
        #pragma unroll
        for (int j = 0; j < 8; j++) acc[i][j] = 0.f;

    for (int k0 = 0; k0 < K; k0 += 8) {
        float4 av = *(const float4*)(Aptr + k0);
        float4 bv = *(const float4*)(Bptr + k0);
        As[ac + 0][arow] = av.x; As[ac + 1][arow] = av.y;
        As[ac + 2][arow] = av.z; As[ac + 3][arow] = av.w;
        Bs[ac + 0][arow] = bv.x; Bs[ac + 1][arow] = bv.y;
        Bs[ac + 2][arow] = bv.z; Bs[ac + 3][arow] = bv.w;
        __syncthreads();

        #pragma unroll
        for (int kk = 0; kk < 8; kk++) {
            float4 a0 = *(const float4*)&As[kk][ty * 8 + 0];
            float4 a1 = *(const float4*)&As[kk][ty * 8 + 4];
            float4 b0 = *(const float4*)&Bs[kk][tx * 8 + 0];
            float4 b1 = *(const float4*)&Bs[kk][tx * 8 + 4];
            float a[8] = {a0.x, a0.y, a0.z, a0.w, a1.x, a1.y, a1.z, a1.w};
            float b[8] = {b0.x, b0.y, b0.z, b0.w, b1.x, b1.y, b1.z, b1.w};
            #pragma unroll
            for (int i = 0; i < 8; i++)
                #pragma unroll
                for (int j = 0; j < 8; j++)
                    acc[i][j] += a[i] * b[j];
        }
        __syncthreads();
    }

    #pragma unroll
    for (int i = 0; i < 8; i++) {
        float4 v0 = make_float4(acc[i][0], acc[i][1], acc[i][2], acc[i][3]);
        float4 v1 = make_float4(acc[i][4], acc[i][5], acc[i][6], acc[i][7]);
        float* crow = C + (size_t)(m0 + ty * 8 + i) * N + n0 + tx * 8;
        *(float4*)(crow + 0) = v0;
        *(float4*)(crow + 4) = v1;
    }
}

// ---------------------------------------------------------------------------
// Flash-style causal attention, fp32.
// grid: (S/64, B*H). block: 256 threads = 16x16, each thread owns a 4x4 tile.
// Q and K are stored d-major (transposed) in smem so the S = Q K^T inner loop
// is an outer-product over d with conflict-free float4 reads.
// ---------------------------------------------------------------------------
#define APAD 68   // row stride (floats) for 64-wide tiles

__global__ __launch_bounds__(256, 1)
void attn_kernel(const float* __restrict__ q, const float* __restrict__ k,
                 const float* __restrict__ v, float* __restrict__ o) {
    extern __shared__ float sm[];
    float* QsT = sm;                 // [64 d][APAD seq]
    float* KsT = sm + 64 * APAD;     // [64 d][APAD key]
    float* Vs  = sm + 2 * 64 * APAD; // [64 key][APAD d]
    float* Ps  = sm + 3 * 64 * APAD; // [64 qrow][APAD key]

    const int qt = blockIdx.x;            // q tile index (0..31)
    const int bh = blockIdx.y;            // b*H + h
    const int b  = bh >> 4;
    const int h  = bh & 15;

    const int tid = threadIdx.x;
    const int tx  = tid & 15;   // key / hd column group
    const int ty  = tid >> 4;   // q row group

    const float* qbase = q + (size_t)b * SS * DD + h * HD;
    const float* kbase = k + (size_t)b * SS * DD + h * HD;
    const float* vbase = v + (size_t)b * SS * DD + h * HD;

    // Load Q tile transposed: QsT[d][seq]
    for (int idx = tid; idx < 64 * 16; idx += 256) {
        int seq = idx & 63;
        int d4  = idx >> 6;
        float4 t = *(const float4*)(qbase + (size_t)(qt * 64 + seq) * DD + d4 * 4);
        QsT[(d4 * 4 + 0) * APAD + seq] = t.x;
        QsT[(d4 * 4 + 1) * APAD + seq] = t.y;
        QsT[(d4 * 4 + 2) * APAD + seq] = t.z;
        QsT[(d4 * 4 + 3) * APAD + seq] = t.w;
    }

    float m_r[4], l_r[4], o_acc[4][4];
    #pragma unroll
    for (int r = 0; r < 4; r++) {
        m_r[r] = -INFINITY; l_r[r] = 0.f;
        #pragma unroll
        for (int c = 0; c < 4; c++) o_acc[r][c] = 0.f;
    }

    for (int jt = 0; jt <= qt; jt++) {
        __syncthreads();  // previous iteration done reading KsT/Vs/Ps

        // K transposed: KsT[d][key]
        for (int idx = tid; idx < 64 * 16; idx += 256) {
            int seq = idx & 63;
            int d4  = idx >> 6;
            float4 t = *(const float4*)(kbase + (size_t)(jt * 64 + seq) * DD + d4 * 4);
            KsT[(d4 * 4 + 0) * APAD + seq] = t.x;
            KsT[(d4 * 4 + 1) * APAD + seq] = t.y;
            KsT[(d4 * 4 + 2) * APAD + seq] = t.z;
            KsT[(d4 * 4 + 3) * APAD + seq] = t.w;
        }
        // V natural: Vs[key][d]
        for (int idx = tid; idx < 64 * 16; idx += 256) {
            int key = idx >> 4;
            int c4  = idx & 15;
            float4 t = *(const float4*)(vbase + (size_t)(jt * 64 + key) * DD + c4 * 4);
            *(float4*)&Vs[key * APAD + c4 * 4] = t;
        }
        __syncthreads();

        // S = Q K^T over this tile (outer product over d)
        float sreg[4][4];
        #pragma unroll
        for (int r = 0; r < 4; r++)
            #pragma unroll
            for (int c = 0; c < 4; c++) sreg[r][c] = 0.f;

        #pragma unroll 4
        for (int d = 0; d < 64; d++) {
            float4 kf = *(const float4*)&KsT[d * APAD + tx * 4];
            float q0 = QsT[d * APAD + ty * 4 + 0];
            float q1 = QsT[d * APAD + ty * 4 + 1];
            float q2 = QsT[d * APAD + ty * 4 + 2];
            float q3 = QsT[d * APAD + ty * 4 + 3];
            sreg[0][0] += q0 * kf.x; sreg[0][1] += q0 * kf.y;
            sreg[0][2] += q0 * kf.z; sreg[0][3] += q0 * kf.w;
            sreg[1][0] += q1 * kf.x; sreg[1][1] += q1 * kf.y;
            sreg[1][2] += q1 * kf.z; sreg[1][3] += q1 * kf.w;
            sreg[2][0] += q2 * kf.x; sreg[2][1] += q2 * kf.y;
            sreg[2][2] += q2 * kf.z; sreg[2][3] += q2 * kf.w;
            sreg[3][0] += q3 * kf.x; sreg[3][1] += q3 * kf.y;
            sreg[3][2] += q3 * kf.z; sreg[3][3] += q3 * kf.w;
        }

        const bool diag = (jt == qt);
        #pragma unroll
        for (int r = 0; r < 4; r++) {
            #pragma unroll
            for (int c = 0; c < 4; c++) {
                float sv = sreg[r][c] * 0.125f;  // 1/sqrt(64)
                if (diag && (ty * 4 + r) < (tx * 4 + c)) sv = -INFINITY;
                sreg[r][c] = sv;
            }
        }

        // Online softmax per row (16-lane segments share a row group)
        #pragma unroll
        for (int r = 0; r < 4; r++) {
            float mx = fmaxf(fmaxf(sreg[r][0], sreg[r][1]),
                             fmaxf(sreg[r][2], sreg[r][3]));
            #pragma unroll
            for (int off = 8; off >= 1; off >>= 1)
                mx = fmaxf(mx, __shfl_xor_sync(0xffffffffu, mx, off, 16));
            float mnew  = fmaxf(m_r[r], mx);
            float alpha = __expf(m_r[r] - mnew);
            float psum = 0.f;
            #pragma unroll
            for (int c = 0; c < 4; c++) {
                float p = __expf(sreg[r][c] - mnew);
                sreg[r][c] = p;
                psum += p;
            }
            #pragma unroll
            for (int off = 8; off >= 1; off >>= 1)
                psum += __shfl_xor_sync(0xffffffffu, psum, off, 16);
            l_r[r] = l_r[r] * alpha + psum;
            m_r[r] = mnew;
            #pragma unroll
            for (int c = 0; c < 4; c++) o_acc[r][c] *= alpha;
            *(float4*)&Ps[(ty * 4 + r) * APAD + tx * 4] =
                make_float4(sreg[r][0], sreg[r][1], sreg[r][2], sreg[r][3]);
        }
        __syncthreads();  // Ps visible to all

        // O += P V
        #pragma unroll 4
        for (int j = 0; j < 64; j++) {
            float4 vf = *(const float4*)&Vs[j * APAD + tx * 4];
            float p0 = Ps[(ty * 4 + 0) * APAD + j];
            float p1 = Ps[(ty * 4 + 1) * APAD + j];
            float p2 = Ps[(ty * 4 + 2) * APAD + j];
            float p3 = Ps[(ty * 4 + 3) * APAD + j];
            o_acc[0][0] += p0 * vf.x; o_acc[0][1] += p0 * vf.y;
            o_acc[0][2] += p0 * vf.z; o_acc[0][3] += p0 * vf.w;
            o_acc[1][0] += p1 * vf.x; o_acc[1][1] += p1 * vf.y;
            o_acc[1][2] += p1 * vf.z; o_acc[1][3] += p1 * vf.w;
            o_acc[2][0] += p2 * vf.x; o_acc[2][1] += p2 * vf.y;
            o_acc[2][2] += p2 * vf.z; o_acc[2][3] += p2 * vf.w;
            o_acc[3][0] += p3 * vf.x; o_acc[3][1] += p3 * vf.y;
            o_acc[3][2] += p3 * vf.z; o_acc[3][3] += p3 * vf.w;
        }
    }

    // Epilogue: normalize and store to (b, s, h*HD + d) layout
    #pragma unroll
    for (int r = 0; r < 4; r++) {
        float inv = 1.f / l_r[r];
        float4 out = make_float4(o_acc[r][0] * inv, o_acc[r][1] * inv,
                                 o_acc[r][2] * inv, o_acc[r][3] * inv);
        float* dst = o + (size_t)(b * SS + qt * 64 + ty * 4 + r) * DD
                       + h * HD + tx * 4;
        *(float4*)dst = out;
    }
}

// ---------------------------------------------------------------------------
extern "C" void kernel_launch(void* const* d_in, const int* in_sizes, int n_in,
                              void* d_out, int out_size) {
    const float* x  = (const float*)d_in[0];
    const float* Wq = (const float*)d_in[1];
    const float* Wk = (const float*)d_in[2];
    const float* Wv = (const float*)d_in[3];
    const float* Wo = (const float*)d_in[4];
    float* out = (float*)d_out;

    void *qp, *kp, *vp, *ap;
    cudaGetSymbolAddress(&qp, g_q);
    cudaGetSymbolAddress(&kp, g_k);
    cudaGetSymbolAddress(&vp, g_v);
    cudaGetSymbolAddress(&ap, g_att);

    dim3 gemm_grid(DD / 128, MTOT / 128);   // (8, 32)
    gemm_nt_kernel<<<gemm_grid, 256>>>(x, Wq, (float*)qp, MTOT, DD, DD);
    gemm_nt_kernel<<<gemm_grid, 256>>>(x, Wk, (float*)kp, MTOT, DD, DD);
    gemm_nt_kernel<<<gemm_grid, 256>>>(x, Wv, (float*)vp, MTOT, DD, DD);

    const int smem_bytes = 4 * 64 * APAD * sizeof(float);  // 69632
    cudaFuncSetAttribute(attn_kernel,
                         cudaFuncAttributeMaxDynamicSharedMemorySize, smem_bytes);
    attn_kernel<<<dim3(SS / 64, BB * HH), 256, smem_bytes>>>(
        (const float*)qp, (const float*)kp, (const float*)vp, (float*)ap);

    gemm_nt_kernel<<<gemm_grid, 256>>>((const float*)ap, Wo, out, MTOT, DD, DD);
}

// round 3
// speedup vs baseline: 1.4519x; 1.4519x over previous
#include <cuda_runtime.h>
#include <cuda_bf16.h>
#include <math.h>
#include <stdint.h>

#define BB 2
#define SS 2048
#define DD 1024
#define HH 16
#define HD 64
#define MTOT (BB*SS)   // 4096 rows

// ---------------------------------------------------------------------------
// Scratch (allocation-free rule: device globals)
// ---------------------------------------------------------------------------
__device__ float g_q[MTOT*DD];
__device__ float g_k[MTOT*DD];
__device__ float g_v[MTOT*DD];
__device__ float g_att[MTOT*DD];
__device__ __nv_bfloat16 g_xhi[MTOT*DD], g_xlo[MTOT*DD];
__device__ __nv_bfloat16 g_whi[4*DD*DD], g_wlo[4*DD*DD];
__device__ __nv_bfloat16 g_ahi[MTOT*DD], g_alo[MTOT*DD];

// ---------------------------------------------------------------------------
// PTX helpers (target-agnostic: mma.sync / ldmatrix / cp.async only)
// ---------------------------------------------------------------------------
__device__ __forceinline__ uint32_t smem_u32(const void* p) {
    uint32_t a;
    asm("{ .reg .u64 t; cvta.to.shared.u64 t, %1; cvt.u32.u64 %0, t; }"
        : "=r"(a) : "l"(p));
    return a;
}
#define CP16(s, g) \
    asm volatile("cp.async.cg.shared.global [%0], [%1], 16;" \
                 :: "r"(s), "l"(g) : "memory")
#define CP_COMMIT() asm volatile("cp.async.commit_group;" ::: "memory")
#define CP_WAIT0()  asm volatile("cp.async.wait_group 0;" ::: "memory")
#define LDSM4(r, addr) \
    asm volatile("ldmatrix.sync.aligned.m8n8.x4.shared.b16 {%0,%1,%2,%3}, [%4];" \
                 : "=r"((r)[0]), "=r"((r)[1]), "=r"((r)[2]), "=r"((r)[3]) \
                 : "r"(addr))
#define MMA_BF16(c, a, b0, b1) \
    asm volatile("mma.sync.aligned.m16n8k16.row.col.f32.bf16.bf16.f32 " \
                 "{%0,%1,%2,%3}, {%4,%5,%6,%7}, {%8,%9}, {%0,%1,%2,%3};" \
                 : "+f"((c)[0]), "+f"((c)[1]), "+f"((c)[2]), "+f"((c)[3]) \
                 : "r"((a)[0]), "r"((a)[1]), "r"((a)[2]), "r"((a)[3]), \
                   "r"(b0), "r"(b1))

// ---------------------------------------------------------------------------
// Split fp32 -> bf16 hi + bf16 lo residual
// ---------------------------------------------------------------------------
__global__ void split_kernel(const float* __restrict__ in,
                             __nv_bfloat16* __restrict__ hi,
                             __nv_bfloat16* __restrict__ lo, int n4) {
    int i = blockIdx.x * blockDim.x + threadIdx.x;
    if (i >= n4) return;
    float4 v = ((const float4*)in)[i];
    __nv_bfloat16 h0 = __float2bfloat16_rn(v.x);
    __nv_bfloat16 h1 = __float2bfloat16_rn(v.y);
    __nv_bfloat16 h2 = __float2bfloat16_rn(v.z);
    __nv_bfloat16 h3 = __float2bfloat16_rn(v.w);
    __nv_bfloat16 l0 = __float2bfloat16_rn(v.x - __bfloat162float(h0));
    __nv_bfloat16 l1 = __float2bfloat16_rn(v.y - __bfloat162float(h1));
    __nv_bfloat16 l2 = __float2bfloat16_rn(v.z - __bfloat162float(h2));
    __nv_bfloat16 l3 = __float2bfloat16_rn(v.w - __bfloat162float(h3));
    __nv_bfloat162* hp = (__nv_bfloat162*)hi;
    __nv_bfloat162* lp = (__nv_bfloat162*)lo;
    hp[2*i]   = __nv_bfloat162(h0, h1);
    hp[2*i+1] = __nv_bfloat162(h2, h3);
    lp[2*i]   = __nv_bfloat162(l0, l1);
    lp[2*i+1] = __nv_bfloat162(l2, l3);
}

// ---------------------------------------------------------------------------
// HMMA split-precision GEMM: C[M,N] = A[M,K] * B[N,K]^T
//   A,B given as bf16 hi/lo pairs; result effectively fp32-accurate:
//   a*b ~= ahi*bhi + alo*bhi + ahi*blo (lo*lo dropped, ~2^-18 relative).
// CTA tile 128x128, BK=32, 8 warps (warp tile 32x64), cp.async double buffer.
// Smem row stride = 40 bf16 (80 B) -> ldmatrix conflict-free.
// ---------------------------------------------------------------------------
#define GM 4096
#define GN 1024
#define GK 1024
#define RS 40                    // smem row stride in bf16
#define MAT_BYTES (128*RS*2)     // 10240 B per matrix tile
#define OFF_AHI 0
#define OFF_ALO (1*MAT_BYTES)
#define OFF_BHI (2*MAT_BYTES)
#define OFF_BLO (3*MAT_BYTES)
#define BUFSTRIDE (4*MAT_BYTES)  // 40960
#define GEMM_SMEM (2*BUFSTRIDE)  // 81920

__device__ __forceinline__ void issue_chunk(
    const __nv_bfloat16* __restrict__ Ahi, const __nv_bfloat16* __restrict__ Alo,
    const __nv_bfloat16* __restrict__ Bhi, const __nv_bfloat16* __restrict__ Blo,
    int m0, int n0, int kc, uint32_t sbuf, int tid)
{
    #pragma unroll
    for (int t = 0; t < 2; t++) {
        int idx = tid + t * 256;
        int row = idx >> 2;            // 0..127
        int c8  = (idx & 3) * 8;       // bf16 col within 32-wide chunk
        size_t ga = (size_t)(m0 + row) * GK + kc + c8;
        size_t gb = (size_t)(n0 + row) * GK + kc + c8;
        uint32_t so = row * (RS * 2) + c8 * 2;
        CP16(sbuf + OFF_AHI + so, Ahi + ga);
        CP16(sbuf + OFF_ALO + so, Alo + ga);
        CP16(sbuf + OFF_BHI + so, Bhi + gb);
        CP16(sbuf + OFF_BLO + so, Blo + gb);
    }
}

__global__ __launch_bounds__(256, 1)
void gemm_mma(const __nv_bfloat16* __restrict__ Ahi, const __nv_bfloat16* __restrict__ Alo,
              const __nv_bfloat16* __restrict__ Bhi, const __nv_bfloat16* __restrict__ Blo,
              float* __restrict__ C)
{
    extern __shared__ char dsm[];
    const uint32_t sb = smem_u32(dsm);

    const int tid  = threadIdx.x;
    const int lane = tid & 31;
    const int wid  = tid >> 5;
    const int wm   = (wid >> 1) * 32;   // warp M offset (4 warps in M)
    const int wn   = (wid & 1) * 64;    // warp N offset (2 warps in N)
    const int m0   = blockIdx.y * 128;
    const int n0   = blockIdx.x * 128;

    // ldmatrix lane address components
    const int mrowA = (lane & 7) + 8 * ((lane >> 3) & 1);
    const int khA   = (lane >> 4) & 1;
    const int nrowB = (lane & 7) + 8 * ((lane >> 4) & 1);
    const int khB   = (lane >> 3) & 1;

    float acc[2][8][4];
    #pragma unroll
    for (int mt = 0; mt < 2; mt++)
        #pragma unroll
        for (int nt = 0; nt < 8; nt++)
            #pragma unroll
            for (int i = 0; i < 4; i++) acc[mt][nt][i] = 0.f;

    issue_chunk(Ahi, Alo, Bhi, Blo, m0, n0, 0, sb, tid);
    CP_COMMIT();

    const int NCH = GK / 32;   // 32 chunks
    for (int c = 0; c < NCH; c++) {
        CP_WAIT0();
        __syncthreads();
        if (c + 1 < NCH) {
            issue_chunk(Ahi, Alo, Bhi, Blo, m0, n0, (c + 1) * 32,
                        sb + ((c + 1) & 1) * BUFSTRIDE, tid);
            CP_COMMIT();
        }
        const uint32_t bu = sb + (c & 1) * BUFSTRIDE;

        #pragma unroll
        for (int ks = 0; ks < 2; ks++) {
            const uint32_t koff = ks * 32;   // 16 bf16 = 32 bytes
            uint32_t ah[2][4], al[2][4];
            #pragma unroll
            for (int mt = 0; mt < 2; mt++) {
                uint32_t arow = (wm + mt * 16 + mrowA) * (RS * 2) + khA * 16 + koff;
                LDSM4(ah[mt], bu + OFF_AHI + arow);
                LDSM4(al[mt], bu + OFF_ALO + arow);
            }
            #pragma unroll
            for (int np = 0; np < 4; np++) {   // pairs of n8 tiles
                uint32_t bh[4], bl[4];
                uint32_t brow = (wn + np * 16 + nrowB) * (RS * 2) + khB * 16 + koff;
                LDSM4(bh, bu + OFF_BHI + brow);
                LDSM4(bl, bu + OFF_BLO + brow);
                #pragma unroll
                for (int mt = 0; mt < 2; mt++) {
                    #pragma unroll
                    for (int s = 0; s < 2; s++) {
                        float* cc = acc[mt][np * 2 + s];
                        MMA_BF16(cc, ah[mt], bh[2*s], bh[2*s+1]);
                        MMA_BF16(cc, al[mt], bh[2*s], bh[2*s+1]);
                        MMA_BF16(cc, ah[mt], bl[2*s], bl[2*s+1]);
                    }
                }
            }
        }
        __syncthreads();
    }

    // Epilogue
    const int r1 = lane >> 2;
    const int cc = (lane & 3) * 2;
    #pragma unroll
    for (int mt = 0; mt < 2; mt++) {
        #pragma unroll
        for (int nt = 0; nt < 8; nt++) {
            float* base = C + (size_t)(m0 + wm + mt * 16) * GN + n0 + wn + nt * 8;
            *(float2*)&base[(size_t)r1 * GN + cc] =
                make_float2(acc[mt][nt][0], acc[mt][nt][1]);
            *(float2*)&base[(size_t)(r1 + 8) * GN + cc] =
                make_float2(acc[mt][nt][2], acc[mt][nt][3]);
        }
    }
}

// ---------------------------------------------------------------------------
// Flash-style causal attention, fp32 (K/V register prefetch, reversed order).
// ---------------------------------------------------------------------------
#define APAD 68

__global__ __launch_bounds__(256, 1)
void attn_kernel(const float* __restrict__ q, const float* __restrict__ k,
                 const float* __restrict__ v, float* __restrict__ o) {
    extern __shared__ float sm[];
    float* QsT = sm;
    float* KsT = sm + 64 * APAD;
    float* Vs  = sm + 2 * 64 * APAD;
    float* Ps  = sm + 3 * 64 * APAD;

    const int qt = gridDim.x - 1 - blockIdx.x;   // long blocks first
    const int bh = blockIdx.y;
    const int b  = bh >> 4;
    const int h  = bh & 15;

    const int tid = threadIdx.x;
    const int tx  = tid & 15;
    const int ty  = tid >> 4;

    const float* qbase = q + (size_t)b * SS * DD + h * HD;
    const float* kbase = k + (size_t)b * SS * DD + h * HD;
    const float* vbase = v + (size_t)b * SS * DD + h * HD;

    for (int idx = tid; idx < 64 * 16; idx += 256) {
        int seq = idx & 63;
        int d4  = idx >> 6;
        float4 t = *(const float4*)(qbase + (size_t)(qt * 64 + seq) * DD + d4 * 4);
        QsT[(d4 * 4 + 0) * APAD + seq] = t.x;
        QsT[(d4 * 4 + 1) * APAD + seq] = t.y;
        QsT[(d4 * 4 + 2) * APAD + seq] = t.z;
        QsT[(d4 * 4 + 3) * APAD + seq] = t.w;
    }

    float m_r[4], l_r[4], o_acc[4][4];
    #pragma unroll
    for (int r = 0; r < 4; r++) {
        m_r[r] = -INFINITY; l_r[r] = 0.f;
        #pragma unroll
        for (int c = 0; c < 4; c++) o_acc[r][c] = 0.f;
    }

    const int kseq = tid & 63, kd4 = tid >> 6;
    const int vkey = tid >> 4, vc4 = tid & 15;
    float4 kreg[4], vreg[4];
    #pragma unroll
    for (int i = 0; i < 4; i++) {
        kreg[i] = *(const float4*)(kbase + (size_t)kseq * DD + (kd4 + 4*i) * 4);
        vreg[i] = *(const float4*)(vbase + (size_t)(vkey + 16*i) * DD + vc4 * 4);
    }

    for (int jt = 0; jt <= qt; jt++) {
        __syncthreads();

        #pragma unroll
        for (int i = 0; i < 4; i++) {
            int d4 = kd4 + 4 * i;
            KsT[(d4 * 4 + 0) * APAD + kseq] = kreg[i].x;
            KsT[(d4 * 4 + 1) * APAD + kseq] = kreg[i].y;
            KsT[(d4 * 4 + 2) * APAD + kseq] = kreg[i].z;
            KsT[(d4 * 4 + 3) * APAD + kseq] = kreg[i].w;
            *(float4*)&Vs[(vkey + 16*i) * APAD + vc4 * 4] = vreg[i];
        }
        if (jt < qt) {
            #pragma unroll
            for (int i = 0; i < 4; i++) {
                kreg[i] = *(const float4*)(kbase + (size_t)((jt+1) * 64 + kseq) * DD + (kd4 + 4*i) * 4);
                vreg[i] = *(const float4*)(vbase + (size_t)((jt+1) * 64 + vkey + 16*i) * DD + vc4 * 4);
            }
        }
        __syncthreads();

        float sreg[4][4];
        #pragma unroll
        for (int r = 0; r < 4; r++)
            #pragma unroll
            for (int c = 0; c < 4; c++) sreg[r][c] = 0.f;

        #pragma unroll 4
        for (int d = 0; d < 64; d++) {
            float4 kf = *(const float4*)&KsT[d * APAD + tx * 4];
            float q0 = QsT[d * APAD + ty * 4 + 0];
            float q1 = QsT[d * APAD + ty * 4 + 1];
            float q2 = QsT[d * APAD + ty * 4 + 2];
            float q3 = QsT[d * APAD + ty * 4 + 3];
            sreg[0][0] += q0 * kf.x; sreg[0][1] += q0 * kf.y;
            sreg[0][2] += q0 * kf.z; sreg[0][3] += q0 * kf.w;
            sreg[1][0] += q1 * kf.x; sreg[1][1] += q1 * kf.y;
            sreg[1][2] += q1 * kf.z; sreg[1][3] += q1 * kf.w;
            sreg[2][0] += q2 * kf.x; sreg[2][1] += q2 * kf.y;
            sreg[2][2] += q2 * kf.z; sreg[2][3] += q2 * kf.w;
            sreg[3][0] += q3 * kf.x; sreg[3][1] += q3 * kf.y;
            sreg[3][2] += q3 * kf.z; sreg[3][3] += q3 * kf.w;
        }

        const bool diag = (jt == qt);
        #pragma unroll
        for (int r = 0; r < 4; r++) {
            #pragma unroll
            for (int c = 0; c < 4; c++) {
                float sv = sreg[r][c] * 0.125f;
                if (diag && (ty * 4 + r) < (tx * 4 + c)) sv = -INFINITY;
                sreg[r][c] = sv;
            }
        }

        #pragma unroll
        for (int r = 0; r < 4; r++) {
            float mx = fmaxf(fmaxf(sreg[r][0], sreg[r][1]),
                             fmaxf(sreg[r][2], sreg[r][3]));
            #pragma unroll
            for (int off = 8; off >= 1; off >>= 1)
                mx = fmaxf(mx, __shfl_xor_sync(0xffffffffu, mx, off, 16));
            float mnew  = fmaxf(m_r[r], mx);
            float alpha = __expf(m_r[r] - mnew);
            float psum = 0.f;
            #pragma unroll
            for (int c = 0; c < 4; c++) {
                float p = __expf(sreg[r][c] - mnew);
                sreg[r][c] = p;
                psum += p;
            }
            #pragma unroll
            for (int off = 8; off >= 1; off >>= 1)
                psum += __shfl_xor_sync(0xffffffffu, psum, off, 16);
            l_r[r] = l_r[r] * alpha + psum;
            m_r[r] = mnew;
            #pragma unroll
            for (int c = 0; c < 4; c++) o_acc[r][c] *= alpha;
            *(float4*)&Ps[(ty * 4 + r) * APAD + tx * 4] =
                make_float4(sreg[r][0], sreg[r][1], sreg[r][2], sreg[r][3]);
        }
        __syncthreads();

        #pragma unroll 4
        for (int j = 0; j < 64; j++) {
            float4 vf = *(const float4*)&Vs[j * APAD + tx * 4];
            float p0 = Ps[(ty * 4 + 0) * APAD + j];
            float p1 = Ps[(ty * 4 + 1) * APAD + j];
            float p2 = Ps[(ty * 4 + 2) * APAD + j];
            float p3 = Ps[(ty * 4 + 3) * APAD + j];
            o_acc[0][0] += p0 * vf.x; o_acc[0][1] += p0 * vf.y;
            o_acc[0][2] += p0 * vf.z; o_acc[0][3] += p0 * vf.w;
            o_acc[1][0] += p1 * vf.x; o_acc[1][1] += p1 * vf.y;
            o_acc[1][2] += p1 * vf.z; o_acc[1][3] += p1 * vf.w;
            o_acc[2][0] += p2 * vf.x; o_acc[2][1] += p2 * vf.y;
            o_acc[2][2] += p2 * vf.z; o_acc[2][3] += p2 * vf.w;
            o_acc[3][0] += p3 * vf.x; o_acc[3][1] += p3 * vf.y;
            o_acc[3][2] += p3 * vf.z; o_acc[3][3] += p3 * vf.w;
        }
    }

    #pragma unroll
    for (int r = 0; r < 4; r++) {
        float inv = 1.f / l_r[r];
        float4 out = make_float4(o_acc[r][0] * inv, o_acc[r][1] * inv,
                                 o_acc[r][2] * inv, o_acc[r][3] * inv);
        float* dst = o + (size_t)(b * SS + qt * 64 + ty * 4 + r) * DD
                       + h * HD + tx * 4;
        *(float4*)dst = out;
    }
}

// ---------------------------------------------------------------------------
extern "C" void kernel_launch(void* const* d_in, const int* in_sizes, int n_in,
                              void* d_out, int out_size) {
    const float* x  = (const float*)d_in[0];
    const float* Wq = (const float*)d_in[1];
    const float* Wk = (const float*)d_in[2];
    const float* Wv = (const float*)d_in[3];
    const float* Wo = (const float*)d_in[4];
    float* out = (float*)d_out;

    void *qp, *kp, *vp, *ap;
    void *xhip, *xlop, *whip, *wlop, *ahip, *alop;
    cudaGetSymbolAddress(&qp, g_q);
    cudaGetSymbolAddress(&kp, g_k);
    cudaGetSymbolAddress(&vp, g_v);
    cudaGetSymbolAddress(&ap, g_att);
    cudaGetSymbolAddress(&xhip, g_xhi);
    cudaGetSymbolAddress(&xlop, g_xlo);
    cudaGetSymbolAddress(&whip, g_whi);
    cudaGetSymbolAddress(&wlop, g_wlo);
    cudaGetSymbolAddress(&ahip, g_ahi);
    cudaGetSymbolAddress(&alop, g_alo);

    __nv_bfloat16* xhi = (__nv_bfloat16*)xhip;
    __nv_bfloat16* xlo = (__nv_bfloat16*)xlop;
    __nv_bfloat16* whi = (__nv_bfloat16*)whip;
    __nv_bfloat16* wlo = (__nv_bfloat16*)wlop;
    __nv_bfloat16* ahi = (__nv_bfloat16*)ahip;
    __nv_bfloat16* alo = (__nv_bfloat16*)alop;

    const int xn4 = MTOT * DD / 4;
    const int wn4 = DD * DD / 4;
    split_kernel<<<xn4 / 256, 256>>>(x, xhi, xlo, xn4);
    split_kernel<<<wn4 / 256, 256>>>(Wq, whi + 0*DD*DD, wlo + 0*DD*DD, wn4);
    split_kernel<<<wn4 / 256, 256>>>(Wk, whi + 1*DD*DD, wlo + 1*DD*DD, wn4);
    split_kernel<<<wn4 / 256, 256>>>(Wv, whi + 2*DD*DD, wlo + 2*DD*DD, wn4);
    split_kernel<<<wn4 / 256, 256>>>(Wo, whi + 3*DD*DD, wlo + 3*DD*DD, wn4);

    cudaFuncSetAttribute(gemm_mma,
                         cudaFuncAttributeMaxDynamicSharedMemorySize, GEMM_SMEM);
    dim3 ggrid(GN / 128, GM / 128);   // (8, 32)
    gemm_mma<<<ggrid, 256, GEMM_SMEM>>>(xhi, xlo, whi + 0*DD*DD, wlo + 0*DD*DD, (float*)qp);
    gemm_mma<<<ggrid, 256, GEMM_SMEM>>>(xhi, xlo, whi + 1*DD*DD, wlo + 1*DD*DD, (float*)kp);
    gemm_mma<<<ggrid, 256, GEMM_SMEM>>>(xhi, xlo, whi + 2*DD*DD, wlo + 2*DD*DD, (float*)vp);

    const int attn_smem = 4 * 64 * APAD * sizeof(float);
    cudaFuncSetAttribute(attn_kernel,
                         cudaFuncAttributeMaxDynamicSharedMemorySize, attn_smem);
    attn_kernel<<<dim3(SS / 64, BB * HH), 256, attn_smem>>>(
        (const float*)qp, (const float*)kp, (const float*)vp, (float*)ap);

    split_kernel<<<xn4 / 256, 256>>>((const float*)ap, ahi, alo, xn4);
    gemm_mma<<<ggrid, 256, GEMM_SMEM>>>(ahi, alo, whi + 3*DD*DD, wlo + 3*DD*DD, out);
}

// round 4
// speedup vs baseline: 2.7426x; 1.8890x over previous
#include <cuda_runtime.h>
#include <cuda_bf16.h>
#include <math.h>
#include <stdint.h>

#define BB 2
#define SS 2048
#define DD 1024
#define HH 16
#define HD 64
#define MTOT (BB*SS)   // 4096 rows

// ---------------------------------------------------------------------------
// Scratch (allocation-free rule: device globals) — all bf16 hi/lo pairs
// ---------------------------------------------------------------------------
__device__ __nv_bfloat16 g_xhi[MTOT*DD], g_xlo[MTOT*DD];
__device__ __nv_bfloat16 g_whi[4*DD*DD], g_wlo[4*DD*DD];
__device__ __nv_bfloat16 g_qhi[MTOT*DD], g_qlo[MTOT*DD];
__device__ __nv_bfloat16 g_khi[MTOT*DD], g_klo[MTOT*DD];
__device__ __nv_bfloat16 g_vhi[MTOT*DD], g_vlo[MTOT*DD];
__device__ __nv_bfloat16 g_ahi[MTOT*DD], g_alo[MTOT*DD];

// ---------------------------------------------------------------------------
// PTX helpers (target-agnostic: mma.sync / ldmatrix / cp.async only)
// ---------------------------------------------------------------------------
__device__ __forceinline__ uint32_t smem_u32(const void* p) {
    uint32_t a;
    asm("{ .reg .u64 t; cvta.to.shared.u64 t, %1; cvt.u32.u64 %0, t; }"
        : "=r"(a) : "l"(p));
    return a;
}
#define CP16(s, g) \
    asm volatile("cp.async.cg.shared.global [%0], [%1], 16;" \
                 :: "r"(s), "l"(g) : "memory")
#define CP_COMMIT() asm volatile("cp.async.commit_group;" ::: "memory")
#define CP_WAIT0()  asm volatile("cp.async.wait_group 0;" ::: "memory")
#define LDSM4(r, addr) \
    asm volatile("ldmatrix.sync.aligned.m8n8.x4.shared.b16 {%0,%1,%2,%3}, [%4];" \
                 : "=r"((r)[0]), "=r"((r)[1]), "=r"((r)[2]), "=r"((r)[3]) \
                 : "r"(addr))
#define LDSM4T(r, addr) \
    asm volatile("ldmatrix.sync.aligned.m8n8.x4.trans.shared.b16 {%0,%1,%2,%3}, [%4];" \
                 : "=r"((r)[0]), "=r"((r)[1]), "=r"((r)[2]), "=r"((r)[3]) \
                 : "r"(addr))
#define MMA_BF16(c, a, b0, b1) \
    asm volatile("mma.sync.aligned.m16n8k16.row.col.f32.bf16.bf16.f32 " \
                 "{%0,%1,%2,%3}, {%4,%5,%6,%7}, {%8,%9}, {%0,%1,%2,%3};" \
                 : "+f"((c)[0]), "+f"((c)[1]), "+f"((c)[2]), "+f"((c)[3]) \
                 : "r"((a)[0]), "r"((a)[1]), "r"((a)[2]), "r"((a)[3]), \
                   "r"(b0), "r"(b1))

__device__ __forceinline__ uint32_t pack_bf16(float x, float y) {
    __nv_bfloat162 t = __floats2bfloat162_rn(x, y);
    return *(uint32_t*)&t;
}

// ---------------------------------------------------------------------------
// Split fp32 -> bf16 hi + bf16 lo residual (inputs x, W only)
// ---------------------------------------------------------------------------
__global__ void split_kernel(const float* __restrict__ in,
                             __nv_bfloat16* __restrict__ hi,
                             __nv_bfloat16* __restrict__ lo, int n4) {
    int i = blockIdx.x * blockDim.x + threadIdx.x;
    if (i >= n4) return;
    float4 v = ((const float4*)in)[i];
    __nv_bfloat16 h0 = __float2bfloat16_rn(v.x);
    __nv_bfloat16 h1 = __float2bfloat16_rn(v.y);
    __nv_bfloat16 h2 = __float2bfloat16_rn(v.z);
    __nv_bfloat16 h3 = __float2bfloat16_rn(v.w);
    ((uint32_t*)hi)[2*i]   = pack_bf16(v.x, v.y);
    ((uint32_t*)hi)[2*i+1] = pack_bf16(v.z, v.w);
    ((uint32_t*)lo)[2*i]   = pack_bf16(v.x - __bfloat162float(h0),
                                       v.y - __bfloat162float(h1));
    ((uint32_t*)lo)[2*i+1] = pack_bf16(v.z - __bfloat162float(h2),
                                       v.w - __bfloat162float(h3));
}

// ---------------------------------------------------------------------------
// HMMA split-precision GEMM: C = A * B^T (hi/lo bf16 operands).
// OUTMODE 0: fp32 C.  OUTMODE 1: bf16 hi/lo C (feeds the next stage).
// ---------------------------------------------------------------------------
#define GM 4096
#define GN 1024
#define GK 1024
#define RS 40
#define MAT_BYTES (128*RS*2)
#define OFF_AHI 0
#define OFF_ALO (1*MAT_BYTES)
#define OFF_BHI (2*MAT_BYTES)
#define OFF_BLO (3*MAT_BYTES)
#define BUFSTRIDE (4*MAT_BYTES)
#define GEMM_SMEM (2*BUFSTRIDE)   // 81920

__device__ __forceinline__ void issue_chunk(
    const __nv_bfloat16* __restrict__ Ahi, const __nv_bfloat16* __restrict__ Alo,
    const __nv_bfloat16* __restrict__ Bhi, const __nv_bfloat16* __restrict__ Blo,
    int m0, int n0, int kc, uint32_t sbuf, int tid)
{
    #pragma unroll
    for (int t = 0; t < 2; t++) {
        int idx = tid + t * 256;
        int row = idx >> 2;
        int c8  = (idx & 3) * 8;
        size_t ga = (size_t)(m0 + row) * GK + kc + c8;
        size_t gb = (size_t)(n0 + row) * GK + kc + c8;
        uint32_t so = row * (RS * 2) + c8 * 2;
        CP16(sbuf + OFF_AHI + so, Ahi + ga);
        CP16(sbuf + OFF_ALO + so, Alo + ga);
        CP16(sbuf + OFF_BHI + so, Bhi + gb);
        CP16(sbuf + OFF_BLO + so, Blo + gb);
    }
}

template<int OUTMODE>
__global__ __launch_bounds__(256, 1)
void gemm_mma(const __nv_bfloat16* __restrict__ Ahi, const __nv_bfloat16* __restrict__ Alo,
              const __nv_bfloat16* __restrict__ Bhi, const __nv_bfloat16* __restrict__ Blo,
              float* __restrict__ C,
              __nv_bfloat16* __restrict__ Chi, __nv_bfloat16* __restrict__ Clo)
{
    extern __shared__ char dsm[];
    const uint32_t sb = smem_u32(dsm);

    const int tid  = threadIdx.x;
    const int lane = tid & 31;
    const int wid  = tid >> 5;
    const int wm   = (wid >> 1) * 32;
    const int wn   = (wid & 1) * 64;
    const int m0   = blockIdx.y * 128;
    const int n0   = blockIdx.x * 128;

    const int mrowA = (lane & 7) + 8 * ((lane >> 3) & 1);
    const int khA   = (lane >> 4) & 1;
    const int nrowB = (lane & 7) + 8 * ((lane >> 4) & 1);
    const int khB   = (lane >> 3) & 1;

    float acc[2][8][4];
    #pragma unroll
    for (int mt = 0; mt < 2; mt++)
        #pragma unroll
        for (int nt = 0; nt < 8; nt++)
            #pragma unroll
            for (int i = 0; i < 4; i++) acc[mt][nt][i] = 0.f;

    issue_chunk(Ahi, Alo, Bhi, Blo, m0, n0, 0, sb, tid);
    CP_COMMIT();

    const int NCH = GK / 32;
    for (int c = 0; c < NCH; c++) {
        CP_WAIT0();
        __syncthreads();
        if (c + 1 < NCH) {
            issue_chunk(Ahi, Alo, Bhi, Blo, m0, n0, (c + 1) * 32,
                        sb + ((c + 1) & 1) * BUFSTRIDE, tid);
            CP_COMMIT();
        }
        const uint32_t bu = sb + (c & 1) * BUFSTRIDE;

        #pragma unroll
        for (int ks = 0; ks < 2; ks++) {
            const uint32_t koff = ks * 32;
            uint32_t ah[2][4], al[2][4];
            #pragma unroll
            for (int mt = 0; mt < 2; mt++) {
                uint32_t arow = (wm + mt * 16 + mrowA) * (RS * 2) + khA * 16 + koff;
                LDSM4(ah[mt], bu + OFF_AHI + arow);
                LDSM4(al[mt], bu + OFF_ALO + arow);
            }
            #pragma unroll
            for (int np = 0; np < 4; np++) {
                uint32_t bh[4], bl[4];
                uint32_t brow = (wn + np * 16 + nrowB) * (RS * 2) + khB * 16 + koff;
                LDSM4(bh, bu + OFF_BHI + brow);
                LDSM4(bl, bu + OFF_BLO + brow);
                #pragma unroll
                for (int mt = 0; mt < 2; mt++) {
                    #pragma unroll
                    for (int s = 0; s < 2; s++) {
                        float* cc = acc[mt][np * 2 + s];
                        MMA_BF16(cc, ah[mt], bh[2*s], bh[2*s+1]);
                        MMA_BF16(cc, al[mt], bh[2*s], bh[2*s+1]);
                        MMA_BF16(cc, ah[mt], bl[2*s], bl[2*s+1]);
                    }
                }
            }
        }
        __syncthreads();
    }

    const int r1 = lane >> 2;
    const int cc = (lane & 3) * 2;
    #pragma unroll
    for (int mt = 0; mt < 2; mt++) {
        #pragma unroll
        for (int nt = 0; nt < 8; nt++) {
            size_t base = (size_t)(m0 + wm + mt * 16) * GN + n0 + wn + nt * 8 + cc;
            if (OUTMODE == 0) {
                *(float2*)&C[base + (size_t)r1 * GN] =
                    make_float2(acc[mt][nt][0], acc[mt][nt][1]);
                *(float2*)&C[base + (size_t)(r1 + 8) * GN] =
                    make_float2(acc[mt][nt][2], acc[mt][nt][3]);
            } else {
                #pragma unroll
                for (int r = 0; r < 2; r++) {
                    float p0 = acc[mt][nt][2*r], p1 = acc[mt][nt][2*r+1];
                    __nv_bfloat16 h0 = __float2bfloat16_rn(p0);
                    __nv_bfloat16 h1 = __float2bfloat16_rn(p1);
                    size_t a = base + (size_t)(r1 + 8*r) * GN;
                    *(uint32_t*)&Chi[a] = pack_bf16(p0, p1);
                    *(uint32_t*)&Clo[a] = pack_bf16(p0 - __bfloat162float(h0),
                                                    p1 - __bfloat162float(h1));
                }
            }
        }
    }
}

// ---------------------------------------------------------------------------
// Tensor-core flash attention (split-precision bf16 mma).
// CTA: 128 q rows (8 warps x 16), key tile 64, double-buffered K/V hi/lo.
// ---------------------------------------------------------------------------
#define KSTR 144                 // smem row stride in bytes (72 bf16)
#define TILE_B (64*KSTR)         // 9216 per operand tile
#define AT_QOFF 0                // Q hi/lo staging: 2 * 128*KSTR = 36864
#define AT_KV   36864
#define AT_BUF  (4*TILE_B)       // 36864 per buffer (Khi,Klo,Vhi,Vlo)
#define ATT_SMEM (AT_KV + 2*AT_BUF)   // 110592

__global__ __launch_bounds__(256, 1)
void attn_mma(const __nv_bfloat16* __restrict__ qhi, const __nv_bfloat16* __restrict__ qlo,
              const __nv_bfloat16* __restrict__ khi, const __nv_bfloat16* __restrict__ klo,
              const __nv_bfloat16* __restrict__ vhi, const __nv_bfloat16* __restrict__ vlo,
              __nv_bfloat16* __restrict__ ohi, __nv_bfloat16* __restrict__ olo)
{
    extern __shared__ char dsm[];
    const uint32_t sQ  = smem_u32(dsm);
    const uint32_t sKV = sQ + AT_KV;

    const int tid  = threadIdx.x;
    const int lane = tid & 31;
    const int wid  = tid >> 5;
    const int qt   = gridDim.x - 1 - blockIdx.x;   // long blocks first
    const int bh   = blockIdx.y;
    const int b    = bh >> 4;
    const int h    = bh & 15;
    const int q0   = qt * 128;

    const size_t gbase = (size_t)b * SS * DD + h * HD;

    // ---- stage Q (hi/lo) into smem ----
    #pragma unroll
    for (int i = 0; i < 8; i++) {
        int idx = tid + i * 256;
        int v   = idx & 1023;
        int row = v >> 3;
        int c8  = (v & 7) * 8;
        const __nv_bfloat16* src = (i < 4) ? qhi : qlo;
        CP16(sQ + (i < 4 ? 0 : 128*KSTR) + row * KSTR + c8 * 2,
             src + gbase + (size_t)(q0 + row) * DD + c8);
    }
    CP_COMMIT();
    CP_WAIT0();
    __syncthreads();

    // ---- issue first K/V tile load ----
    {
        #pragma unroll
        for (int i = 0; i < 8; i++) {
            int idx = tid + i * 256;
            int v   = idx & 511;
            int row = v >> 3;
            int c8  = (v & 7) * 8;
            int arr = i >> 1;
            const __nv_bfloat16* src = (arr == 0) ? khi : (arr == 1) ? klo
                                     : (arr == 2) ? vhi : vlo;
            CP16(sKV + arr * TILE_B + row * KSTR + c8 * 2,
                 src + gbase + (size_t)row * DD + c8);
        }
        CP_COMMIT();
    }

    // ---- load Q frags to registers ----
    const int wq    = wid * 16;
    const int mrowA = (lane & 7) + 8 * ((lane >> 3) & 1);
    const int khA   = (lane >> 4) & 1;
    uint32_t qfh[4][4], qfl[4][4];
    #pragma unroll
    for (int t = 0; t < 4; t++) {
        uint32_t a = sQ + (wq + mrowA) * KSTR + khA * 16 + t * 32;
        LDSM4(qfh[t], a);
        LDSM4(qfl[t], a + 128*KSTR);
    }

    float oacc[8][4];
    #pragma unroll
    for (int n = 0; n < 8; n++)
        #pragma unroll
        for (int i = 0; i < 4; i++) oacc[n][i] = 0.f;
    float mrow[2] = {-INFINITY, -INFINITY};
    float lrow[2] = {0.f, 0.f};

    const int nrowB = (lane & 7) + 8 * ((lane >> 4) & 1);
    const int khB   = (lane >> 3) & 1;
    const int vrow  = (lane & 7) + 8 * ((lane >> 3) & 1);
    const int vcol8 = ((lane >> 4) & 1) * 8;
    const int r1    = lane >> 2;
    const int c2    = (lane & 3) * 2;

    const int ntiles = 2 * qt + 2;
    for (int kt = 0; kt < ntiles; kt++) {
        CP_WAIT0();
        __syncthreads();
        if (kt + 1 < ntiles) {
            uint32_t nbuf = sKV + ((kt + 1) & 1) * AT_BUF;
            #pragma unroll
            for (int i = 0; i < 8; i++) {
                int idx = tid + i * 256;
                int v   = idx & 511;
                int row = v >> 3;
                int c8  = (v & 7) * 8;
                int arr = i >> 1;
                const __nv_bfloat16* src = (arr == 0) ? khi : (arr == 1) ? klo
                                         : (arr == 2) ? vhi : vlo;
                CP16(nbuf + arr * TILE_B + row * KSTR + c8 * 2,
                     src + gbase + (size_t)((kt + 1) * 64 + row) * DD + c8);
            }
            CP_COMMIT();
        }
        const uint32_t bu = sKV + (kt & 1) * AT_BUF;

        // ---- S = Q K^T (3-term split) ----
        float s[8][4];
        #pragma unroll
        for (int j = 0; j < 8; j++)
            #pragma unroll
            for (int i = 0; i < 4; i++) s[j][i] = 0.f;

        #pragma unroll
        for (int t = 0; t < 4; t++) {
            #pragma unroll
            for (int j2 = 0; j2 < 4; j2++) {
                uint32_t kh[4], kl[4];
                uint32_t brow = (j2 * 16 + nrowB) * KSTR + khB * 16 + t * 32;
                LDSM4(kh, bu + brow);
                LDSM4(kl, bu + TILE_B + brow);
                #pragma unroll
                for (int s2 = 0; s2 < 2; s2++) {
                    float* cc = s[j2 * 2 + s2];
                    MMA_BF16(cc, qfh[t], kh[2*s2], kh[2*s2+1]);
                    MMA_BF16(cc, qfl[t], kh[2*s2], kh[2*s2+1]);
                    MMA_BF16(cc, qfh[t], kl[2*s2], kl[2*s2+1]);
                }
            }
        }

        // ---- scale + causal mask ----
        const bool masked = (kt >= ntiles - 2);
        #pragma unroll
        for (int j = 0; j < 8; j++) {
            #pragma unroll
            for (int i = 0; i < 4; i++) {
                float sv = s[j][i] * 0.125f;
                if (masked) {
                    int qrow = q0 + wq + r1 + ((i >> 1) << 3);
                    int key  = kt * 64 + j * 8 + c2 + (i & 1);
                    if (key > qrow) sv = -INFINITY;
                }
                s[j][i] = sv;
            }
        }

        // ---- online softmax (rows r1, r1+8) ----
        #pragma unroll
        for (int r = 0; r < 2; r++) {
            float mx = -INFINITY;
            #pragma unroll
            for (int j = 0; j < 8; j++)
                mx = fmaxf(mx, fmaxf(s[j][2*r], s[j][2*r+1]));
            mx = fmaxf(mx, __shfl_xor_sync(0xffffffffu, mx, 1));
            mx = fmaxf(mx, __shfl_xor_sync(0xffffffffu, mx, 2));
            float mnew  = fmaxf(mrow[r], mx);
            float alpha = __expf(mrow[r] - mnew);
            float psum = 0.f;
            #pragma unroll
            for (int j = 0; j < 8; j++) {
                float p0 = __expf(s[j][2*r]   - mnew);
                float p1 = __expf(s[j][2*r+1] - mnew);
                s[j][2*r] = p0; s[j][2*r+1] = p1;
                psum += p0 + p1;
            }
            psum += __shfl_xor_sync(0xffffffffu, psum, 1);
            psum += __shfl_xor_sync(0xffffffffu, psum, 2);
            lrow[r] = lrow[r] * alpha + psum;
            mrow[r] = mnew;
            #pragma unroll
            for (int n = 0; n < 8; n++) {
                oacc[n][2*r]   *= alpha;
                oacc[n][2*r+1] *= alpha;
            }
        }

        // ---- pack P into A-frags (hi/lo) ----
        uint32_t ph[4][4], pl[4][4];
        #pragma unroll
        for (int t = 0; t < 4; t++) {
            #pragma unroll
            for (int half = 0; half < 2; half++) {   // n8 tile 2t, 2t+1
                int j = 2 * t + half;
                #pragma unroll
                for (int r = 0; r < 2; r++) {
                    float p0 = s[j][2*r], p1 = s[j][2*r+1];
                    __nv_bfloat16 h0 = __float2bfloat16_rn(p0);
                    __nv_bfloat16 h1 = __float2bfloat16_rn(p1);
                    ph[t][half*2 + r] = pack_bf16(p0, p1);
                    pl[t][half*2 + r] = pack_bf16(p0 - __bfloat162float(h0),
                                                  p1 - __bfloat162float(h1));
                }
            }
        }

        // ---- O += P V (3-term split), V via ldmatrix.trans ----
        #pragma unroll
        for (int t = 0; t < 4; t++) {     // k16 tiles over 64 keys
            #pragma unroll
            for (int n2 = 0; n2 < 4; n2++) {
                uint32_t vh[4], vl[4];
                uint32_t va = (t * 16 + vrow) * KSTR + (n2 * 16 + vcol8) * 2;
                LDSM4T(vh, bu + 2 * TILE_B + va);
                LDSM4T(vl, bu + 3 * TILE_B + va);
                #pragma unroll
                for (int s2 = 0; s2 < 2; s2++) {
                    float* cc = oacc[n2 * 2 + s2];
                    MMA_BF16(cc, ph[t], vh[2*s2], vh[2*s2+1]);
                    MMA_BF16(cc, pl[t], vh[2*s2], vh[2*s2+1]);
                    MMA_BF16(cc, ph[t], vl[2*s2], vl[2*s2+1]);
                }
            }
        }
    }

    // ---- epilogue: normalize, write bf16 hi/lo ----
    #pragma unroll
    for (int r = 0; r < 2; r++) {
        float linv = 1.f / lrow[r];
        int qrow = q0 + wq + r1 + 8 * r;
        size_t base = (size_t)(b * SS + qrow) * DD + h * HD + c2;
        #pragma unroll
        for (int n = 0; n < 8; n++) {
            float p0 = oacc[n][2*r] * linv;
            float p1 = oacc[n][2*r+1] * linv;
            __nv_bfloat16 h0 = __float2bfloat16_rn(p0);
            __nv_bfloat16 h1 = __float2bfloat16_rn(p1);
            *(uint32_t*)&ohi[base + n * 8] = pack_bf16(p0, p1);
            *(uint32_t*)&olo[base + n * 8] = pack_bf16(p0 - __bfloat162float(h0),
                                                       p1 - __bfloat162float(h1));
        }
    }
}

// ---------------------------------------------------------------------------
extern "C" void kernel_launch(void* const* d_in, const int* in_sizes, int n_in,
                              void* d_out, int out_size) {
    const float* x  = (const float*)d_in[0];
    const float* Wq = (const float*)d_in[1];
    const float* Wk = (const float*)d_in[2];
    const float* Wv = (const float*)d_in[3];
    const float* Wo = (const float*)d_in[4];
    float* out = (float*)d_out;

    void *p_xhi, *p_xlo, *p_whi, *p_wlo;
    void *p_qhi, *p_qlo, *p_khi, *p_klo, *p_vhi, *p_vlo, *p_ahi, *p_alo;
    cudaGetSymbolAddress(&p_xhi, g_xhi);
    cudaGetSymbolAddress(&p_xlo, g_xlo);
    cudaGetSymbolAddress(&p_whi, g_whi);
    cudaGetSymbolAddress(&p_wlo, g_wlo);
    cudaGetSymbolAddress(&p_qhi, g_qhi);
    cudaGetSymbolAddress(&p_qlo, g_qlo);
    cudaGetSymbolAddress(&p_khi, g_khi);
    cudaGetSymbolAddress(&p_klo, g_klo);
    cudaGetSymbolAddress(&p_vhi, g_vhi);
    cudaGetSymbolAddress(&p_vlo, g_vlo);
    cudaGetSymbolAddress(&p_ahi, g_ahi);
    cudaGetSymbolAddress(&p_alo, g_alo);

    __nv_bfloat16* xhi = (__nv_bfloat16*)p_xhi;
    __nv_bfloat16* xlo = (__nv_bfloat16*)p_xlo;
    __nv_bfloat16* whi = (__nv_bfloat16*)p_whi;
    __nv_bfloat16* wlo = (__nv_bfloat16*)p_wlo;
    __nv_bfloat16* qhi = (__nv_bfloat16*)p_qhi;
    __nv_bfloat16* qlo = (__nv_bfloat16*)p_qlo;
    __nv_bfloat16* khi = (__nv_bfloat16*)p_khi;
    __nv_bfloat16* klo = (__nv_bfloat16*)p_klo;
    __nv_bfloat16* vhi = (__nv_bfloat16*)p_vhi;
    __nv_bfloat16* vlo = (__nv_bfloat16*)p_vlo;
    __nv_bfloat16* ahi = (__nv_bfloat16*)p_ahi;
    __nv_bfloat16* alo = (__nv_bfloat16*)p_alo;

    const int xn4 = MTOT * DD / 4;
    const int wn4 = DD * DD / 4;
    split_kernel<<<xn4 / 256, 256>>>(x, xhi, xlo, xn4);
    split_kernel<<<wn4 / 256, 256>>>(Wq, whi + 0*DD*DD, wlo + 0*DD*DD, wn4);
    split_kernel<<<wn4 / 256, 256>>>(Wk, whi + 1*DD*DD, wlo + 1*DD*DD, wn4);
    split_kernel<<<wn4 / 256, 256>>>(Wv, whi + 2*DD*DD, wlo + 2*DD*DD, wn4);
    split_kernel<<<wn4 / 256, 256>>>(Wo, whi + 3*DD*DD, wlo + 3*DD*DD, wn4);

    cudaFuncSetAttribute(gemm_mma<0>,
                         cudaFuncAttributeMaxDynamicSharedMemorySize, GEMM_SMEM);
    cudaFuncSetAttribute(gemm_mma<1>,
                         cudaFuncAttributeMaxDynamicSharedMemorySize, GEMM_SMEM);
    dim3 ggrid(GN / 128, GM / 128);
    gemm_mma<1><<<ggrid, 256, GEMM_SMEM>>>(xhi, xlo, whi + 0*DD*DD, wlo + 0*DD*DD,
                                           nullptr, qhi, qlo);
    gemm_mma<1><<<ggrid, 256, GEMM_SMEM>>>(xhi, xlo, whi + 1*DD*DD, wlo + 1*DD*DD,
                                           nullptr, khi, klo);
    gemm_mma<1><<<ggrid, 256, GEMM_SMEM>>>(xhi, xlo, whi + 2*DD*DD, wlo + 2*DD*DD,
                                           nullptr, vhi, vlo);

    cudaFuncSetAttribute(attn_mma,
                         cudaFuncAttributeMaxDynamicSharedMemorySize, ATT_SMEM);
    attn_mma<<<dim3(SS / 128, BB * HH), 256, ATT_SMEM>>>(
        qhi, qlo, khi, klo, vhi, vlo, ahi, alo);

    gemm_mma<0><<<ggrid, 256, GEMM_SMEM>>>(ahi, alo, whi + 3*DD*DD, wlo + 3*DD*DD,
                                           out, nullptr, nullptr);
}

// round 5
// speedup vs baseline: 3.0026x; 1.0948x over previous
#include <cuda_runtime.h>
#include <cuda_bf16.h>
#include <math.h>
#include <stdint.h>

#define BB 2
#define SS 2048
#define DD 1024
#define HH 16
#define HD 64
#define MTOT (BB*SS)   // 4096 rows
#define QKVN 3072      // fused QKV output width

// ---------------------------------------------------------------------------
// Scratch (allocation-free rule: device globals) — all bf16 hi/lo pairs
// ---------------------------------------------------------------------------
__device__ __nv_bfloat16 g_xhi[MTOT*DD], g_xlo[MTOT*DD];
__device__ __nv_bfloat16 g_whi[4*DD*DD], g_wlo[4*DD*DD];
__device__ __nv_bfloat16 g_qkvhi[MTOT*QKVN], g_qkvlo[MTOT*QKVN];
__device__ __nv_bfloat16 g_ahi[MTOT*DD], g_alo[MTOT*DD];

// ---------------------------------------------------------------------------
// PTX helpers (target-agnostic: mma.sync / ldmatrix / cp.async only)
// ---------------------------------------------------------------------------
__device__ __forceinline__ uint32_t smem_u32(const void* p) {
    uint32_t a;
    asm("{ .reg .u64 t; cvta.to.shared.u64 t, %1; cvt.u32.u64 %0, t; }"
        : "=r"(a) : "l"(p));
    return a;
}
#define CP16(s, g) \
    asm volatile("cp.async.cg.shared.global [%0], [%1], 16;" \
                 :: "r"(s), "l"(g) : "memory")
#define CP_COMMIT() asm volatile("cp.async.commit_group;" ::: "memory")
#define CP_WAIT0()  asm volatile("cp.async.wait_group 0;" ::: "memory")
#define LDSM4(r, addr) \
    asm volatile("ldmatrix.sync.aligned.m8n8.x4.shared.b16 {%0,%1,%2,%3}, [%4];" \
                 : "=r"((r)[0]), "=r"((r)[1]), "=r"((r)[2]), "=r"((r)[3]) \
                 : "r"(addr))
#define LDSM4T(r, addr) \
    asm volatile("ldmatrix.sync.aligned.m8n8.x4.trans.shared.b16 {%0,%1,%2,%3}, [%4];" \
                 : "=r"((r)[0]), "=r"((r)[1]), "=r"((r)[2]), "=r"((r)[3]) \
                 : "r"(addr))
#define MMA_BF16(c, a, b0, b1) \
    asm volatile("mma.sync.aligned.m16n8k16.row.col.f32.bf16.bf16.f32 " \
                 "{%0,%1,%2,%3}, {%4,%5,%6,%7}, {%8,%9}, {%0,%1,%2,%3};" \
                 : "+f"((c)[0]), "+f"((c)[1]), "+f"((c)[2]), "+f"((c)[3]) \
                 : "r"((a)[0]), "r"((a)[1]), "r"((a)[2]), "r"((a)[3]), \
                   "r"(b0), "r"(b1))

__device__ __forceinline__ uint32_t pack_bf16(float x, float y) {
    __nv_bfloat162 t = __floats2bfloat162_rn(x, y);
    return *(uint32_t*)&t;
}

// ---------------------------------------------------------------------------
// Split fp32 -> bf16 hi + lo residual. x: one launch; weights: batched launch.
// ---------------------------------------------------------------------------
__device__ __forceinline__ void split4(const float4 v, uint32_t* hi, uint32_t* lo) {
    __nv_bfloat16 h0 = __float2bfloat16_rn(v.x);
    __nv_bfloat16 h1 = __float2bfloat16_rn(v.y);
    __nv_bfloat16 h2 = __float2bfloat16_rn(v.z);
    __nv_bfloat16 h3 = __float2bfloat16_rn(v.w);
    hi[0] = pack_bf16(v.x, v.y);
    hi[1] = pack_bf16(v.z, v.w);
    lo[0] = pack_bf16(v.x - __bfloat162float(h0), v.y - __bfloat162float(h1));
    lo[1] = pack_bf16(v.z - __bfloat162float(h2), v.w - __bfloat162float(h3));
}

__global__ void split_kernel(const float* __restrict__ in,
                             __nv_bfloat16* __restrict__ hi,
                             __nv_bfloat16* __restrict__ lo, int n4) {
    int i = blockIdx.x * blockDim.x + threadIdx.x;
    if (i >= n4) return;
    uint32_t h[2], l[2];
    split4(((const float4*)in)[i], h, l);
    ((uint32_t*)hi)[2*i] = h[0]; ((uint32_t*)hi)[2*i+1] = h[1];
    ((uint32_t*)lo)[2*i] = l[0]; ((uint32_t*)lo)[2*i+1] = l[1];
}

__global__ void wsplit_kernel(const float* __restrict__ w0, const float* __restrict__ w1,
                              const float* __restrict__ w2, const float* __restrict__ w3,
                              __nv_bfloat16* __restrict__ hi,
                              __nv_bfloat16* __restrict__ lo) {
    const int wn4 = DD * DD / 4;
    int idx = blockIdx.x * blockDim.x + threadIdx.x;
    if (idx >= 4 * wn4) return;
    int w = idx / wn4, i = idx - w * wn4;
    const float* src = (w == 0) ? w0 : (w == 1) ? w1 : (w == 2) ? w2 : w3;
    uint32_t h[2], l[2];
    split4(((const float4*)src)[i], h, l);
    ((uint32_t*)hi)[2*idx] = h[0]; ((uint32_t*)hi)[2*idx+1] = h[1];
    ((uint32_t*)lo)[2*idx] = l[0]; ((uint32_t*)lo)[2*idx+1] = l[1];
}

// ---------------------------------------------------------------------------
// HMMA split-precision GEMM: C[M, Nout] = A[M,1024] * B[Nout,1024]^T
// OUTMODE 0: fp32 C.  OUTMODE 1: bf16 hi/lo C.  ldc = Nout (param).
// 128x128 tile, 8 warps, cp.async double buffer, 2 CTAs/SM.
// ---------------------------------------------------------------------------
#define GK 1024
#define RS 40
#define MAT_BYTES (128*RS*2)
#define OFF_AHI 0
#define OFF_ALO (1*MAT_BYTES)
#define OFF_BHI (2*MAT_BYTES)
#define OFF_BLO (3*MAT_BYTES)
#define BUFSTRIDE (4*MAT_BYTES)
#define GEMM_SMEM (2*BUFSTRIDE)   // 81920

__device__ __forceinline__ void issue_chunk(
    const __nv_bfloat16* __restrict__ Ahi, const __nv_bfloat16* __restrict__ Alo,
    const __nv_bfloat16* __restrict__ Bhi, const __nv_bfloat16* __restrict__ Blo,
    int m0, int n0, int kc, uint32_t sbuf, int tid)
{
    #pragma unroll
    for (int t = 0; t < 2; t++) {
        int idx = tid + t * 256;
        int row = idx >> 2;
        int c8  = (idx & 3) * 8;
        size_t ga = (size_t)(m0 + row) * GK + kc + c8;
        size_t gb = (size_t)(n0 + row) * GK + kc + c8;
        uint32_t so = row * (RS * 2) + c8 * 2;
        CP16(sbuf + OFF_AHI + so, Ahi + ga);
        CP16(sbuf + OFF_ALO + so, Alo + ga);
        CP16(sbuf + OFF_BHI + so, Bhi + gb);
        CP16(sbuf + OFF_BLO + so, Blo + gb);
    }
}

template<int OUTMODE>
__global__ __launch_bounds__(256, 2)
void gemm_mma(const __nv_bfloat16* __restrict__ Ahi, const __nv_bfloat16* __restrict__ Alo,
              const __nv_bfloat16* __restrict__ Bhi, const __nv_bfloat16* __restrict__ Blo,
              float* __restrict__ C,
              __nv_bfloat16* __restrict__ Chi, __nv_bfloat16* __restrict__ Clo,
              int ldc)
{
    extern __shared__ char dsm[];
    const uint32_t sb = smem_u32(dsm);

    const int tid  = threadIdx.x;
    const int lane = tid & 31;
    const int wid  = tid >> 5;
    const int wm   = (wid >> 1) * 32;
    const int wn   = (wid & 1) * 64;
    const int m0   = blockIdx.y * 128;
    const int n0   = blockIdx.x * 128;

    const int mrowA = (lane & 7) + 8 * ((lane >> 3) & 1);
    const int khA   = (lane >> 4) & 1;
    const int nrowB = (lane & 7) + 8 * ((lane >> 4) & 1);
    const int khB   = (lane >> 3) & 1;

    float acc[2][8][4];
    #pragma unroll
    for (int mt = 0; mt < 2; mt++)
        #pragma unroll
        for (int nt = 0; nt < 8; nt++)
            #pragma unroll
            for (int i = 0; i < 4; i++) acc[mt][nt][i] = 0.f;

    issue_chunk(Ahi, Alo, Bhi, Blo, m0, n0, 0, sb, tid);
    CP_COMMIT();

    const int NCH = GK / 32;
    for (int c = 0; c < NCH; c++) {
        CP_WAIT0();
        __syncthreads();
        if (c + 1 < NCH) {
            issue_chunk(Ahi, Alo, Bhi, Blo, m0, n0, (c + 1) * 32,
                        sb + ((c + 1) & 1) * BUFSTRIDE, tid);
            CP_COMMIT();
        }
        const uint32_t bu = sb + (c & 1) * BUFSTRIDE;

        #pragma unroll
        for (int ks = 0; ks < 2; ks++) {
            const uint32_t koff = ks * 32;
            uint32_t ah[2][4], al[2][4];
            #pragma unroll
            for (int mt = 0; mt < 2; mt++) {
                uint32_t arow = (wm + mt * 16 + mrowA) * (RS * 2) + khA * 16 + koff;
                LDSM4(ah[mt], bu + OFF_AHI + arow);
                LDSM4(al[mt], bu + OFF_ALO + arow);
            }
            #pragma unroll
            for (int np = 0; np < 4; np++) {
                uint32_t bh[4], bl[4];
                uint32_t brow = (wn + np * 16 + nrowB) * (RS * 2) + khB * 16 + koff;
                LDSM4(bh, bu + OFF_BHI + brow);
                LDSM4(bl, bu + OFF_BLO + brow);
                #pragma unroll
                for (int mt = 0; mt < 2; mt++) {
                    #pragma unroll
                    for (int s = 0; s < 2; s++) {
                        float* cc = acc[mt][np * 2 + s];
                        MMA_BF16(cc, ah[mt], bh[2*s], bh[2*s+1]);
                        MMA_BF16(cc, al[mt], bh[2*s], bh[2*s+1]);
                        MMA_BF16(cc, ah[mt], bl[2*s], bl[2*s+1]);
                    }
                }
            }
        }
        __syncthreads();
    }

    const int r1 = lane >> 2;
    const int cc = (lane & 3) * 2;
    #pragma unroll
    for (int mt = 0; mt < 2; mt++) {
        #pragma unroll
        for (int nt = 0; nt < 8; nt++) {
            size_t base = (size_t)(m0 + wm + mt * 16) * ldc + n0 + wn + nt * 8 + cc;
            if (OUTMODE == 0) {
                *(float2*)&C[base + (size_t)r1 * ldc] =
                    make_float2(acc[mt][nt][0], acc[mt][nt][1]);
                *(float2*)&C[base + (size_t)(r1 + 8) * ldc] =
                    make_float2(acc[mt][nt][2], acc[mt][nt][3]);
            } else {
                #pragma unroll
                for (int r = 0; r < 2; r++) {
                    float p0 = acc[mt][nt][2*r], p1 = acc[mt][nt][2*r+1];
                    __nv_bfloat16 h0 = __float2bfloat16_rn(p0);
                    __nv_bfloat16 h1 = __float2bfloat16_rn(p1);
                    size_t a = base + (size_t)(r1 + 8*r) * ldc;
                    *(uint32_t*)&Chi[a] = pack_bf16(p0, p1);
                    *(uint32_t*)&Clo[a] = pack_bf16(p0 - __bfloat162float(h0),
                                                    p1 - __bfloat162float(h1));
                }
            }
        }
    }
}

// ---------------------------------------------------------------------------
// Tensor-core flash attention (split-precision bf16 mma).
// Q/K/V read from the fused QKV array (row stride QKVN; col offsets 0/1024/2048).
// ---------------------------------------------------------------------------
#define KSTR 144
#define TILE_B (64*KSTR)
#define AT_KV   36864
#define AT_BUF  (4*TILE_B)
#define ATT_SMEM (AT_KV + 2*AT_BUF)   // 110592

__global__ __launch_bounds__(256, 1)
void attn_mma(const __nv_bfloat16* __restrict__ qkvhi,
              const __nv_bfloat16* __restrict__ qkvlo,
              __nv_bfloat16* __restrict__ ohi, __nv_bfloat16* __restrict__ olo)
{
    extern __shared__ char dsm[];
    const uint32_t sQ  = smem_u32(dsm);
    const uint32_t sKV = sQ + AT_KV;

    const int tid  = threadIdx.x;
    const int lane = tid & 31;
    const int wid  = tid >> 5;
    const int qt   = gridDim.x - 1 - blockIdx.x;
    const int bh   = blockIdx.y;
    const int b    = bh >> 4;
    const int h    = bh & 15;
    const int q0   = qt * 128;

    const size_t rowbase = (size_t)b * SS * QKVN + h * HD;
    const __nv_bfloat16* qhi = qkvhi + rowbase;
    const __nv_bfloat16* qlo = qkvlo + rowbase;
    const __nv_bfloat16* khi = qkvhi + rowbase + DD;
    const __nv_bfloat16* klo = qkvlo + rowbase + DD;
    const __nv_bfloat16* vhi = qkvhi + rowbase + 2 * DD;
    const __nv_bfloat16* vlo = qkvlo + rowbase + 2 * DD;

    // ---- stage Q (hi/lo) into smem ----
    #pragma unroll
    for (int i = 0; i < 8; i++) {
        int idx = tid + i * 256;
        int v   = idx & 1023;
        int row = v >> 3;
        int c8  = (v & 7) * 8;
        const __nv_bfloat16* src = (i < 4) ? qhi : qlo;
        CP16(sQ + (i < 4 ? 0 : 128*KSTR) + row * KSTR + c8 * 2,
             src + (size_t)(q0 + row) * QKVN + c8);
    }
    CP_COMMIT();
    CP_WAIT0();
    __syncthreads();

    // ---- issue first K/V tile load ----
    {
        #pragma unroll
        for (int i = 0; i < 8; i++) {
            int idx = tid + i * 256;
            int v   = idx & 511;
            int row = v >> 3;
            int c8  = (v & 7) * 8;
            int arr = i >> 1;
            const __nv_bfloat16* src = (arr == 0) ? khi : (arr == 1) ? klo
                                     : (arr == 2) ? vhi : vlo;
            CP16(sKV + arr * TILE_B + row * KSTR + c8 * 2,
                 src + (size_t)row * QKVN + c8);
        }
        CP_COMMIT();
    }

    // ---- load Q frags to registers ----
    const int wq    = wid * 16;
    const int mrowA = (lane & 7) + 8 * ((lane >> 3) & 1);
    const int khA   = (lane >> 4) & 1;
    uint32_t qfh[4][4], qfl[4][4];
    #pragma unroll
    for (int t = 0; t < 4; t++) {
        uint32_t a = sQ + (wq + mrowA) * KSTR + khA * 16 + t * 32;
        LDSM4(qfh[t], a);
        LDSM4(qfl[t], a + 128*KSTR);
    }

    float oacc[8][4];
    #pragma unroll
    for (int n = 0; n < 8; n++)
        #pragma unroll
        for (int i = 0; i < 4; i++) oacc[n][i] = 0.f;
    float mrow[2] = {-INFINITY, -INFINITY};
    float lrow[2] = {0.f, 0.f};

    const int nrowB = (lane & 7) + 8 * ((lane >> 4) & 1);
    const int khB   = (lane >> 3) & 1;
    const int vrow  = (lane & 7) + 8 * ((lane >> 3) & 1);
    const int vcol8 = ((lane >> 4) & 1) * 8;
    const int r1    = lane >> 2;
    const int c2    = (lane & 3) * 2;

    const int ntiles = 2 * qt + 2;
    for (int kt = 0; kt < ntiles; kt++) {
        CP_WAIT0();
        __syncthreads();
        if (kt + 1 < ntiles) {
            uint32_t nbuf = sKV + ((kt + 1) & 1) * AT_BUF;
            #pragma unroll
            for (int i = 0; i < 8; i++) {
                int idx = tid + i * 256;
                int v   = idx & 511;
                int row = v >> 3;
                int c8  = (v & 7) * 8;
                int arr = i >> 1;
                const __nv_bfloat16* src = (arr == 0) ? khi : (arr == 1) ? klo
                                         : (arr == 2) ? vhi : vlo;
                CP16(nbuf + arr * TILE_B + row * KSTR + c8 * 2,
                     src + (size_t)((kt + 1) * 64 + row) * QKVN + c8);
            }
            CP_COMMIT();
        }
        const uint32_t bu = sKV + (kt & 1) * AT_BUF;

        // ---- S = Q K^T (3-term split) ----
        float s[8][4];
        #pragma unroll
        for (int j = 0; j < 8; j++)
            #pragma unroll
            for (int i = 0; i < 4; i++) s[j][i] = 0.f;

        #pragma unroll
        for (int t = 0; t < 4; t++) {
            #pragma unroll
            for (int j2 = 0; j2 < 4; j2++) {
                uint32_t kh[4], kl[4];
                uint32_t brow = (j2 * 16 + nrowB) * KSTR + khB * 16 + t * 32;
                LDSM4(kh, bu + brow);
                LDSM4(kl, bu + TILE_B + brow);
                #pragma unroll
                for (int s2 = 0; s2 < 2; s2++) {
                    float* cc = s[j2 * 2 + s2];
                    MMA_BF16(cc, qfh[t], kh[2*s2], kh[2*s2+1]);
                    MMA_BF16(cc, qfl[t], kh[2*s2], kh[2*s2+1]);
                    MMA_BF16(cc, qfh[t], kl[2*s2], kl[2*s2+1]);
                }
            }
        }

        // ---- scale + causal mask ----
        const bool masked = (kt >= ntiles - 2);
        #pragma unroll
        for (int j = 0; j < 8; j++) {
            #pragma unroll
            for (int i = 0; i < 4; i++) {
                float sv = s[j][i] * 0.125f;
                if (masked) {
                    int qrow = q0 + wq + r1 + ((i >> 1) << 3);
                    int key  = kt * 64 + j * 8 + c2 + (i & 1);
                    if (key > qrow) sv = -INFINITY;
                }
                s[j][i] = sv;
            }
        }

        // ---- online softmax ----
        #pragma unroll
        for (int r = 0; r < 2; r++) {
            float mx = -INFINITY;
            #pragma unroll
            for (int j = 0; j < 8; j++)
                mx = fmaxf(mx, fmaxf(s[j][2*r], s[j][2*r+1]));
            mx = fmaxf(mx, __shfl_xor_sync(0xffffffffu, mx, 1));
            mx = fmaxf(mx, __shfl_xor_sync(0xffffffffu, mx, 2));
            float mnew  = fmaxf(mrow[r], mx);
            float alpha = __expf(mrow[r] - mnew);
            float psum = 0.f;
            #pragma unroll
            for (int j = 0; j < 8; j++) {
                float p0 = __expf(s[j][2*r]   - mnew);
                float p1 = __expf(s[j][2*r+1] - mnew);
                s[j][2*r] = p0; s[j][2*r+1] = p1;
                psum += p0 + p1;
            }
            psum += __shfl_xor_sync(0xffffffffu, psum, 1);
            psum += __shfl_xor_sync(0xffffffffu, psum, 2);
            lrow[r] = lrow[r] * alpha + psum;
            mrow[r] = mnew;
            #pragma unroll
            for (int n = 0; n < 8; n++) {
                oacc[n][2*r]   *= alpha;
                oacc[n][2*r+1] *= alpha;
            }
        }

        // ---- pack P into A-frags (hi/lo) ----
        uint32_t ph[4][4], pl[4][4];
        #pragma unroll
        for (int t = 0; t < 4; t++) {
            #pragma unroll
            for (int half = 0; half < 2; half++) {
                int j = 2 * t + half;
                #pragma unroll
                for (int r = 0; r < 2; r++) {
                    float p0 = s[j][2*r], p1 = s[j][2*r+1];
                    __nv_bfloat16 h0 = __float2bfloat16_rn(p0);
                    __nv_bfloat16 h1 = __float2bfloat16_rn(p1);
                    ph[t][half*2 + r] = pack_bf16(p0, p1);
                    pl[t][half*2 + r] = pack_bf16(p0 - __bfloat162float(h0),
                                                  p1 - __bfloat162float(h1));
                }
            }
        }

        // ---- O += P V (3-term split) ----
        #pragma unroll
        for (int t = 0; t < 4; t++) {
            #pragma unroll
            for (int n2 = 0; n2 < 4; n2++) {
                uint32_t vh[4], vl[4];
                uint32_t va = (t * 16 + vrow) * KSTR + (n2 * 16 + vcol8) * 2;
                LDSM4T(vh, bu + 2 * TILE_B + va);
                LDSM4T(vl, bu + 3 * TILE_B + va);
                #pragma unroll
                for (int s2 = 0; s2 < 2; s2++) {
                    float* cc = oacc[n2 * 2 + s2];
                    MMA_BF16(cc, ph[t], vh[2*s2], vh[2*s2+1]);
                    MMA_BF16(cc, pl[t], vh[2*s2], vh[2*s2+1]);
                    MMA_BF16(cc, ph[t], vl[2*s2], vl[2*s2+1]);
                }
            }
        }
    }

    // ---- epilogue: normalize, write bf16 hi/lo (stride DD) ----
    #pragma unroll
    for (int r = 0; r < 2; r++) {
        float linv = 1.f / lrow[r];
        int qrow = q0 + wq + r1 + 8 * r;
        size_t base = (size_t)(b * SS + qrow) * DD + h * HD + c2;
        #pragma unroll
        for (int n = 0; n < 8; n++) {
            float p0 = oacc[n][2*r] * linv;
            float p1 = oacc[n][2*r+1] * linv;
            __nv_bfloat16 h0 = __float2bfloat16_rn(p0);
            __nv_bfloat16 h1 = __float2bfloat16_rn(p1);
            *(uint32_t*)&ohi[base + n * 8] = pack_bf16(p0, p1);
            *(uint32_t*)&olo[base + n * 8] = pack_bf16(p0 - __bfloat162float(h0),
                                                       p1 - __bfloat162float(h1));
        }
    }
}

// ---------------------------------------------------------------------------
extern "C" void kernel_launch(void* const* d_in, const int* in_sizes, int n_in,
                              void* d_out, int out_size) {
    const float* x  = (const float*)d_in[0];
    const float* Wq = (const float*)d_in[1];
    const float* Wk = (const float*)d_in[2];
    const float* Wv = (const float*)d_in[3];
    const float* Wo = (const float*)d_in[4];
    float* out = (float*)d_out;

    void *p_xhi, *p_xlo, *p_whi, *p_wlo, *p_qkvhi, *p_qkvlo, *p_ahi, *p_alo;
    cudaGetSymbolAddress(&p_xhi, g_xhi);
    cudaGetSymbolAddress(&p_xlo, g_xlo);
    cudaGetSymbolAddress(&p_whi, g_whi);
    cudaGetSymbolAddress(&p_wlo, g_wlo);
    cudaGetSymbolAddress(&p_qkvhi, g_qkvhi);
    cudaGetSymbolAddress(&p_qkvlo, g_qkvlo);
    cudaGetSymbolAddress(&p_ahi, g_ahi);
    cudaGetSymbolAddress(&p_alo, g_alo);

    __nv_bfloat16* xhi = (__nv_bfloat16*)p_xhi;
    __nv_bfloat16* xlo = (__nv_bfloat16*)p_xlo;
    __nv_bfloat16* whi = (__nv_bfloat16*)p_whi;
    __nv_bfloat16* wlo = (__nv_bfloat16*)p_wlo;
    __nv_bfloat16* qkvhi = (__nv_bfloat16*)p_qkvhi;
    __nv_bfloat16* qkvlo = (__nv_bfloat16*)p_qkvlo;
    __nv_bfloat16* ahi = (__nv_bfloat16*)p_ahi;
    __nv_bfloat16* alo = (__nv_bfloat16*)p_alo;

    const int xn4 = MTOT * DD / 4;
    const int wtot4 = 4 * DD * DD / 4;
    split_kernel<<<xn4 / 256, 256>>>(x, xhi, xlo, xn4);
    wsplit_kernel<<<(wtot4 + 255) / 256, 256>>>(Wq, Wk, Wv, Wo, whi, wlo);

    cudaFuncSetAttribute(gemm_mma<0>,
                         cudaFuncAttributeMaxDynamicSharedMemorySize, GEMM_SMEM);
    cudaFuncSetAttribute(gemm_mma<1>,
                         cudaFuncAttributeMaxDynamicSharedMemorySize, GEMM_SMEM);

    // Fused QKV projection: C[4096, 3072], B = [Wq;Wk;Wv] rows 0..3071 of whi
    gemm_mma<1><<<dim3(QKVN / 128, MTOT / 128), 256, GEMM_SMEM>>>(
        xhi, xlo, whi, wlo, nullptr, qkvhi, qkvlo, QKVN);

    cudaFuncSetAttribute(attn_mma,
                         cudaFuncAttributeMaxDynamicSharedMemorySize, ATT_SMEM);
    attn_mma<<<dim3(SS / 128, BB * HH), 256, ATT_SMEM>>>(qkvhi, qkvlo, ahi, alo);

    gemm_mma<0><<<dim3(DD / 128, MTOT / 128), 256, GEMM_SMEM>>>(
        ahi, alo, whi + 3*DD*DD, wlo + 3*DD*DD, out, nullptr, nullptr, DD);
}